// round 4
// baseline (speedup 1.0000x reference)
#include <cuda_runtime.h>
#include <math.h>

#define NB 8
#define NSEQ 1024
#define NC 768
#define NH 12
#define NDH 64
#define SCALE 0.125f

// Scratch device globals (no allocation allowed in kernel_launch)
__device__ float g_qh[NB * NH * NSEQ * NDH];     // [B,H,N,64]
__device__ float g_kh[NB * NH * NSEQ * NDH];
__device__ float g_vh[NB * NH * NSEQ * NDH];
__device__ float g_fattn[NB * NH * NDH * NDH];   // [B,H,64,64]
__device__ float g_tmp[NB * NSEQ * NC];          // t + f, [B,N,C]

__device__ __forceinline__ unsigned f2tf(float x) {
    unsigned r;
    asm("cvt.rna.tf32.f32 %0, %1;" : "=r"(r) : "f"(x));
    return r;
}
__device__ __forceinline__ void split(float x, unsigned& hi, unsigned& lo) {
    unsigned h = f2tf(x);
    hi = h;
    lo = f2tf(x - __uint_as_float(h));
}

// interleaved (hi,lo) pair accessors; idx in elements
__device__ __forceinline__ uint2 ld2(const unsigned* p, int idx) {
    return *(const uint2*)&p[idx * 2];
}
__device__ __forceinline__ void st2x2(unsigned* p, int idx, float a, float b) {
    unsigned ha, la, hb, lb;
    split(a, ha, la);
    split(b, hb, lb);
    *(uint4*)&p[idx * 2] = make_uint4(ha, la, hb, lb);
}
__device__ __forceinline__ void st4(unsigned* p, int idx, float4 v) {
    st2x2(p, idx, v.x, v.y);
    st2x2(p, idx + 2, v.z, v.w);
}

__device__ __forceinline__ void mma8(float d[4], const unsigned a[4],
                                     unsigned b0, unsigned b1) {
    asm volatile(
        "mma.sync.aligned.m16n8k8.row.col.f32.tf32.tf32.f32 "
        "{%0,%1,%2,%3}, {%4,%5,%6,%7}, {%8,%9}, {%0,%1,%2,%3};"
        : "+f"(d[0]), "+f"(d[1]), "+f"(d[2]), "+f"(d[3])
        : "r"(a[0]), "r"(a[1]), "r"(a[2]), "r"(a[3]), "r"(b0), "r"(b1));
}
// 3xtf32 from pre-split pairs
__device__ __forceinline__ void mma3p(float d[4], const uint2 a[4],
                                      uint2 b0, uint2 b1) {
    unsigned ah[4] = {a[0].x, a[1].x, a[2].x, a[3].x};
    unsigned al[4] = {a[0].y, a[1].y, a[2].y, a[3].y};
    mma8(d, al, b0.x, b1.x);
    mma8(d, ah, b0.y, b1.y);
    mma8(d, ah, b0.x, b1.x);
}

// ---------------------------------------------------------------------------
// Kernel 1: fused QKV projection, 3xtf32 with pre-split smem tiles.
// dsm layout (words): A pairs [128 x 36e] at 0 (9216w), B pairs [32 x 132e] at 9216 (8448w)
// ---------------------------------------------------------------------------
__global__ __launch_bounds__(256) void qkv_gemm(const float* __restrict__ q,
                                                const float* __restrict__ kx,
                                                const float* __restrict__ Wq,
                                                const float* __restrict__ Wkv) {
    extern __shared__ unsigned dsm[];
    unsigned* Asp = dsm;           // elem stride 36
    unsigned* Bsp = dsm + 9216;    // elem stride 132

    const int n0 = blockIdx.x * 128;
    const int m0 = blockIdx.y * 128;
    const bool isQ = (n0 < 768);
    const float* A = isQ ? q : kx;
    const float* Bm;
    int ldb, cb;
    if (isQ) { Bm = Wq;  ldb = 768;  cb = n0; }
    else     { Bm = Wkv; ldb = 1536; cb = n0 - 768; }

    const int t = threadIdx.x, lane = t & 31, w = t >> 5;
    const int g = lane >> 2, tg = lane & 3;
    const int wm = w & 3, wn = w >> 2;
    const int ar = t >> 3, ac = (t & 7) * 4;
    const int br = t >> 3, bc = (t & 7) * 4;

    float acc[2][8][4] = {};
    float4 pa[4], pb[4];

#pragma unroll
    for (int u = 0; u < 4; u++) {
        pa[u] = *(const float4*)(A + (size_t)(m0 + ar + u * 32) * 768 + ac);
        pb[u] = *(const float4*)(Bm + (size_t)br * ldb + cb + bc + u * 32);
    }
#pragma unroll
    for (int u = 0; u < 4; u++) {
        st4(Asp, (ar + u * 32) * 36 + ac, pa[u]);
        st4(Bsp, br * 132 + bc + u * 32, pb[u]);
    }
    __syncthreads();

    for (int k0 = 32; k0 <= 768; k0 += 32) {
        const bool more = (k0 < 768);
        if (more) {
#pragma unroll
            for (int u = 0; u < 4; u++) {
                pa[u] = *(const float4*)(A + (size_t)(m0 + ar + u * 32) * 768 + k0 + ac);
                pb[u] = *(const float4*)(Bm + (size_t)(k0 + br) * ldb + cb + bc + u * 32);
            }
        }
#pragma unroll
        for (int kk = 0; kk < 4; kk++) {
            const int k = kk * 8;
            uint2 af[2][4];
#pragma unroll
            for (int i = 0; i < 2; i++) {
                const int rb = wm * 32 + i * 16 + g;
                af[i][0] = ld2(Asp, rb * 36 + k + tg);
                af[i][1] = ld2(Asp, (rb + 8) * 36 + k + tg);
                af[i][2] = ld2(Asp, rb * 36 + k + tg + 4);
                af[i][3] = ld2(Asp, (rb + 8) * 36 + k + tg + 4);
            }
#pragma unroll
            for (int j = 0; j < 8; j++) {
                const int c = wn * 64 + j * 8 + g;
                uint2 b0 = ld2(Bsp, (k + tg) * 132 + c);
                uint2 b1 = ld2(Bsp, (k + tg + 4) * 132 + c);
                mma3p(acc[0][j], af[0], b0, b1);
                mma3p(acc[1][j], af[1], b0, b1);
            }
        }
        if (more) {
            __syncthreads();
#pragma unroll
            for (int u = 0; u < 4; u++) {
                st4(Asp, (ar + u * 32) * 36 + ac, pa[u]);
                st4(Bsp, br * 132 + bc + u * 32, pb[u]);
            }
            __syncthreads();
        }
    }

#pragma unroll
    for (int i = 0; i < 2; i++) {
        const int mA = m0 + wm * 32 + i * 16 + g;
#pragma unroll
        for (int half = 0; half < 2; half++) {
            const int m = mA + half * 8;
            const int bb = m >> 10, n = m & 1023;
#pragma unroll
            for (int j = 0; j < 8; j++) {
                const int cg = n0 + wn * 64 + j * 8 + tg * 2;
                float2 v = make_float2(acc[i][j][half * 2], acc[i][j][half * 2 + 1]);
                if (cg < 768) {
                    const int h = cg >> 6, d = cg & 63;
                    *(float2*)&g_qh[(((size_t)bb * NH + h) * NSEQ + n) * NDH + d] = v;
                } else {
                    const int cc = cg - 768;
                    const int c2 = (cc >= 768) ? cc - 768 : cc;
                    const int h = c2 >> 6, d = c2 & 63;
                    float* dst = (cc >= 768) ? g_vh : g_kh;
                    *(float2*)&dst[(((size_t)bb * NH + h) * NSEQ + n) * NDH + d] = v;
                }
            }
        }
    }
}

// ---------------------------------------------------------------------------
// Kernel 2: feature attention, 3xtf32, pre-split tiles.
// dsm: Q pairs [32 x 68e] at 0 (4352w), K pairs at 4352 (4352w),
//      Ss f32 [64*65] at 8704, sinv at 12864. total 12928w
// ---------------------------------------------------------------------------
__global__ __launch_bounds__(128) void fattn_kernel() {
    extern __shared__ unsigned dsm[];
    unsigned* Qsp = dsm;           // [n][d] elem stride 68
    unsigned* Ksp = dsm + 4352;
    float* Ss = (float*)(dsm + 8704);
    float* sinv = (float*)(dsm + 12864);

    const int bh = blockIdx.x;
    const float* Q = g_qh + (size_t)bh * NSEQ * NDH;
    const float* K = g_kh + (size_t)bh * NSEQ * NDH;

    const int t = threadIdx.x, lane = t & 31, w = t >> 5;
    const int g = lane >> 2, tg = lane & 3;
    const int lr = t >> 4, lc = (t & 15) * 4;
    const int mb = w * 16 + g;

    float acc[8][4] = {};
    float4 pq[4], pk[4];

#pragma unroll
    for (int u = 0; u < 4; u++) {
        pq[u] = *(const float4*)(Q + (size_t)(lr + u * 8) * 64 + lc);
        pk[u] = *(const float4*)(K + (size_t)(lr + u * 8) * 64 + lc);
    }
#pragma unroll
    for (int u = 0; u < 4; u++) {
        st4(Qsp, (lr + u * 8) * 68 + lc, pq[u]);
        st4(Ksp, (lr + u * 8) * 68 + lc, pk[u]);
    }
    __syncthreads();

    for (int n0 = 32; n0 <= NSEQ; n0 += 32) {
        const bool more = (n0 < NSEQ);
        if (more) {
#pragma unroll
            for (int u = 0; u < 4; u++) {
                pq[u] = *(const float4*)(Q + (size_t)(n0 + lr + u * 8) * 64 + lc);
                pk[u] = *(const float4*)(K + (size_t)(n0 + lr + u * 8) * 64 + lc);
            }
        }
#pragma unroll
        for (int kk = 0; kk < 4; kk++) {
            const int k = kk * 8;
            uint2 a[4];
            a[0] = ld2(Qsp, (k + tg) * 68 + mb);
            a[1] = ld2(Qsp, (k + tg) * 68 + mb + 8);
            a[2] = ld2(Qsp, (k + tg + 4) * 68 + mb);
            a[3] = ld2(Qsp, (k + tg + 4) * 68 + mb + 8);
#pragma unroll
            for (int j = 0; j < 8; j++) {
                const int c = j * 8 + g;
                uint2 b0 = ld2(Ksp, (k + tg) * 68 + c);
                uint2 b1 = ld2(Ksp, (k + tg + 4) * 68 + c);
                mma3p(acc[j], a, b0, b1);
            }
        }
        if (more) {
            __syncthreads();
#pragma unroll
            for (int u = 0; u < 4; u++) {
                st4(Qsp, (lr + u * 8) * 68 + lc, pq[u]);
                st4(Ksp, (lr + u * 8) * 68 + lc, pk[u]);
            }
            __syncthreads();
        }
    }

#pragma unroll
    for (int j = 0; j < 8; j++) {
        const int r0 = w * 16 + g, c = j * 8 + tg * 2;
        Ss[r0 * 65 + c]           = acc[j][0] * SCALE;
        Ss[r0 * 65 + c + 1]       = acc[j][1] * SCALE;
        Ss[(r0 + 8) * 65 + c]     = acc[j][2] * SCALE;
        Ss[(r0 + 8) * 65 + c + 1] = acc[j][3] * SCALE;
    }
    __syncthreads();
    if (t < 64) {
        float mx = -INFINITY;
        for (int e = 0; e < 64; e++) mx = fmaxf(mx, Ss[t * 65 + e]);
        float s = 0.f;
        for (int e = 0; e < 64; e++) {
            float v = __expf(Ss[t * 65 + e] - mx);
            Ss[t * 65 + e] = v;
            s += v;
        }
        sinv[t] = 1.0f / s;
    }
    __syncthreads();
    float* outp = g_fattn + (size_t)bh * 4096;
    for (int idx = t; idx < 4096; idx += 128) {
        const int r = idx >> 6;
        outp[idx] = Ss[r * 65 + (idx & 63)] * sinv[r];
    }
}

// ---------------------------------------------------------------------------
// Kernel 3: flash attention + feature apply, 3xtf32, pre-split K/V/P tiles.
// dsm words: Qstage f32 [64x68] at 0 (4352)  -> feature Fa f32
//            K pairs [32x68e] at 4352 (4352) -> feature Vq f32 overlays 4352..8704
//            V pairs [32x68e] at 8704 (4352)
//            P pairs 4w x [16x36e] at 13056 (4608).  total 17664w
// ---------------------------------------------------------------------------
__global__ __launch_bounds__(128) void attn_kernel() {
    extern __shared__ unsigned dsm[];
    float* Qs = (float*)dsm;            // stage, stride 68
    unsigned* Ksp = dsm + 4352;         // elem stride 68
    unsigned* Vsp = dsm + 8704;         // elem stride 68
    unsigned* Psp = dsm + 13056;        // per warp [16][36e]

    const int bh = blockIdx.y;
    const int n0q = blockIdx.x * 64;
    const float* Qg = g_qh + (size_t)bh * NSEQ * NDH;
    const float* Kg = g_kh + (size_t)bh * NSEQ * NDH;
    const float* Vg = g_vh + (size_t)bh * NSEQ * NDH;

    const int t = threadIdx.x, lane = t & 31, w = t >> 5;
    const int g = lane >> 2, tg = lane & 3;
    const int lr = t >> 4, lc = (t & 15) * 4;

    // stage Q, extract pre-split fragments to registers
#pragma unroll
    for (int u = 0; u < 8; u++)
        *(float4*)&Qs[(lr + u * 8) * 68 + lc] =
            *(const float4*)(Qg + (size_t)(n0q + lr + u * 8) * 64 + lc);
    __syncthreads();
    uint2 qf[8][4];
    {
        const int rb = w * 16 + g;
#pragma unroll
        for (int kk = 0; kk < 8; kk++) {
            const int k = kk * 8;
            split(Qs[rb * 68 + k + tg],           qf[kk][0].x, qf[kk][0].y);
            split(Qs[(rb + 8) * 68 + k + tg],     qf[kk][1].x, qf[kk][1].y);
            split(Qs[rb * 68 + k + tg + 4],       qf[kk][2].x, qf[kk][2].y);
            split(Qs[(rb + 8) * 68 + k + tg + 4], qf[kk][3].x, qf[kk][3].y);
        }
    }
    __syncthreads();

    float O[8][4] = {};
    float mr0 = -INFINITY, mr1 = -INFINITY, l0 = 0.f, l1 = 0.f;
    unsigned* Pw = Psp + w * 16 * 36 * 2;

    float4 pk[4], pv[4];
#pragma unroll
    for (int u = 0; u < 4; u++) {
        pk[u] = *(const float4*)(Kg + (size_t)(lr + u * 8) * 64 + lc);
        pv[u] = *(const float4*)(Vg + (size_t)(lr + u * 8) * 64 + lc);
    }
#pragma unroll
    for (int u = 0; u < 4; u++) {
        st4(Ksp, (lr + u * 8) * 68 + lc, pk[u]);
        st4(Vsp, (lr + u * 8) * 68 + lc, pv[u]);
    }
    __syncthreads();

    for (int c0 = 32; c0 <= NSEQ; c0 += 32) {
        const bool more = (c0 < NSEQ);
        if (more) {
#pragma unroll
            for (int u = 0; u < 4; u++) {
                pk[u] = *(const float4*)(Kg + (size_t)(c0 + lr + u * 8) * 64 + lc);
                pv[u] = *(const float4*)(Vg + (size_t)(c0 + lr + u * 8) * 64 + lc);
            }
        }

        // S = Q K^T
        float sacc[4][4] = {};
#pragma unroll
        for (int kk = 0; kk < 8; kk++) {
            const int k = kk * 8;
#pragma unroll
            for (int j = 0; j < 4; j++) {
                const int c = j * 8 + g;
                uint2 b0 = ld2(Ksp, c * 68 + k + tg);
                uint2 b1 = ld2(Ksp, c * 68 + k + tg + 4);
                mma3p(sacc[j], qf[kk], b0, b1);
            }
        }

        // online softmax (rows g and g+8)
        float mx0 = -INFINITY, mx1 = -INFINITY;
#pragma unroll
        for (int j = 0; j < 4; j++) {
#pragma unroll
            for (int u = 0; u < 4; u++) sacc[j][u] *= SCALE;
            mx0 = fmaxf(mx0, fmaxf(sacc[j][0], sacc[j][1]));
            mx1 = fmaxf(mx1, fmaxf(sacc[j][2], sacc[j][3]));
        }
        mx0 = fmaxf(mx0, __shfl_xor_sync(0xffffffffu, mx0, 1));
        mx0 = fmaxf(mx0, __shfl_xor_sync(0xffffffffu, mx0, 2));
        mx1 = fmaxf(mx1, __shfl_xor_sync(0xffffffffu, mx1, 1));
        mx1 = fmaxf(mx1, __shfl_xor_sync(0xffffffffu, mx1, 2));
        const float mn0 = fmaxf(mr0, mx0), mn1 = fmaxf(mr1, mx1);
        const float co0 = __expf(mr0 - mn0), co1 = __expf(mr1 - mn1);
        float rs0 = 0.f, rs1 = 0.f;
#pragma unroll
        for (int j = 0; j < 4; j++) {
            const float p00 = __expf(sacc[j][0] - mn0);
            const float p01 = __expf(sacc[j][1] - mn0);
            const float p10 = __expf(sacc[j][2] - mn1);
            const float p11 = __expf(sacc[j][3] - mn1);
            rs0 += p00 + p01;
            rs1 += p10 + p11;
            const int c = j * 8 + tg * 2;
            st2x2(Pw, g * 36 + c, p00, p01);
            st2x2(Pw, (g + 8) * 36 + c, p10, p11);
        }
        rs0 += __shfl_xor_sync(0xffffffffu, rs0, 1);
        rs0 += __shfl_xor_sync(0xffffffffu, rs0, 2);
        rs1 += __shfl_xor_sync(0xffffffffu, rs1, 1);
        rs1 += __shfl_xor_sync(0xffffffffu, rs1, 2);
        l0 = l0 * co0 + rs0;
        l1 = l1 * co1 + rs1;
        mr0 = mn0;
        mr1 = mn1;
#pragma unroll
        for (int nt = 0; nt < 8; nt++) {
            O[nt][0] *= co0; O[nt][1] *= co0;
            O[nt][2] *= co1; O[nt][3] *= co1;
        }
        __syncwarp();

        // O += P @ V
#pragma unroll
        for (int kk = 0; kk < 4; kk++) {
            const int k = kk * 8;
            uint2 a[4];
            a[0] = ld2(Pw, g * 36 + k + tg);
            a[1] = ld2(Pw, (g + 8) * 36 + k + tg);
            a[2] = ld2(Pw, g * 36 + k + tg + 4);
            a[3] = ld2(Pw, (g + 8) * 36 + k + tg + 4);
#pragma unroll
            for (int nt = 0; nt < 8; nt++) {
                uint2 b0 = ld2(Vsp, (k + tg) * 68 + nt * 8 + g);
                uint2 b1 = ld2(Vsp, (k + tg + 4) * 68 + nt * 8 + g);
                mma3p(O[nt], a, b0, b1);
            }
        }

        __syncthreads();
        if (more) {
#pragma unroll
            for (int u = 0; u < 4; u++) {
                st4(Ksp, (lr + u * 8) * 68 + lc, pk[u]);
                st4(Vsp, (lr + u * 8) * 68 + lc, pv[u]);
            }
            __syncthreads();
        }
    }

    // normalize token attention
    const float i0 = 1.0f / l0, i1 = 1.0f / l1;
#pragma unroll
    for (int nt = 0; nt < 8; nt++) {
        O[nt][0] *= i0; O[nt][1] *= i0;
        O[nt][2] *= i1; O[nt][3] *= i1;
    }

    // feature path: O[n,d] += sum_e V[n,e] * f_attn[d,e]   (one-shot, inline split)
    float* Fa = (float*)dsm;            // [d][e] stride 68
    float* Vq = (float*)(dsm + 4352);   // [r][e] stride 68
    const float* Fg = g_fattn + (size_t)bh * 4096;
#pragma unroll
    for (int u = 0; u < 8; u++) {
        const int row = lr + u * 8;
        *(float4*)&Fa[row * 68 + lc] = *(const float4*)(Fg + (size_t)row * 64 + lc);
        *(float4*)&Vq[row * 68 + lc] =
            *(const float4*)(Vg + (size_t)(n0q + row) * 64 + lc);
    }
    __syncthreads();
    {
        const int rb = w * 16 + g;
#pragma unroll
        for (int kk = 0; kk < 8; kk++) {
            const int k = kk * 8;
            uint2 a[4];
            split(Vq[rb * 68 + k + tg],           a[0].x, a[0].y);
            split(Vq[(rb + 8) * 68 + k + tg],     a[1].x, a[1].y);
            split(Vq[rb * 68 + k + tg + 4],       a[2].x, a[2].y);
            split(Vq[(rb + 8) * 68 + k + tg + 4], a[3].x, a[3].y);
#pragma unroll
            for (int nt = 0; nt < 8; nt++) {
                uint2 b0, b1;
                split(Fa[(nt * 8 + g) * 68 + k + tg],     b0.x, b0.y);
                split(Fa[(nt * 8 + g) * 68 + k + tg + 4], b1.x, b1.y);
                mma3p(O[nt], a, b0, b1);
            }
        }
    }

    // store t+f into [B,N,C]
    const int bb = bh / NH, h = bh - bb * NH;
    const int r0 = n0q + w * 16 + g;
#pragma unroll
    for (int nt = 0; nt < 8; nt++) {
        const int col = h * 64 + nt * 8 + tg * 2;
        *(float2*)&g_tmp[((size_t)bb * NSEQ + r0) * NC + col] =
            make_float2(O[nt][0], O[nt][1]);
        *(float2*)&g_tmp[((size_t)bb * NSEQ + r0 + 8) * NC + col] =
            make_float2(O[nt][2], O[nt][3]);
    }
}

// ---------------------------------------------------------------------------
// Kernel 4: output projection, 3xtf32, pre-split smem tiles.
// ---------------------------------------------------------------------------
__global__ __launch_bounds__(256) void proj_gemm(const float* __restrict__ W,
                                                 const float* __restrict__ bias,
                                                 float* __restrict__ out) {
    extern __shared__ unsigned dsm[];
    unsigned* Asp = dsm;           // elem stride 36
    unsigned* Bsp = dsm + 9216;    // elem stride 132

    const int n0 = blockIdx.x * 128;
    const int m0 = blockIdx.y * 128;
    const int t = threadIdx.x, lane = t & 31, w = t >> 5;
    const int g = lane >> 2, tg = lane & 3;
    const int wm = w & 3, wn = w >> 2;
    const int ar = t >> 3, ac = (t & 7) * 4;
    const int br = t >> 3, bc = (t & 7) * 4;

    float acc[2][8][4] = {};
    float4 pa[4], pb[4];

#pragma unroll
    for (int u = 0; u < 4; u++) {
        pa[u] = *(const float4*)(g_tmp + (size_t)(m0 + ar + u * 32) * 768 + ac);
        pb[u] = *(const float4*)(W + (size_t)br * 768 + n0 + bc + u * 32);
    }
#pragma unroll
    for (int u = 0; u < 4; u++) {
        st4(Asp, (ar + u * 32) * 36 + ac, pa[u]);
        st4(Bsp, br * 132 + bc + u * 32, pb[u]);
    }
    __syncthreads();

    for (int k0 = 32; k0 <= 768; k0 += 32) {
        const bool more = (k0 < 768);
        if (more) {
#pragma unroll
            for (int u = 0; u < 4; u++) {
                pa[u] = *(const float4*)(g_tmp + (size_t)(m0 + ar + u * 32) * 768 + k0 + ac);
                pb[u] = *(const float4*)(W + (size_t)(k0 + br) * 768 + n0 + bc + u * 32);
            }
        }
#pragma unroll
        for (int kk = 0; kk < 4; kk++) {
            const int k = kk * 8;
            uint2 af[2][4];
#pragma unroll
            for (int i = 0; i < 2; i++) {
                const int rb = wm * 32 + i * 16 + g;
                af[i][0] = ld2(Asp, rb * 36 + k + tg);
                af[i][1] = ld2(Asp, (rb + 8) * 36 + k + tg);
                af[i][2] = ld2(Asp, rb * 36 + k + tg + 4);
                af[i][3] = ld2(Asp, (rb + 8) * 36 + k + tg + 4);
            }
#pragma unroll
            for (int j = 0; j < 8; j++) {
                const int c = wn * 64 + j * 8 + g;
                uint2 b0 = ld2(Bsp, (k + tg) * 132 + c);
                uint2 b1 = ld2(Bsp, (k + tg + 4) * 132 + c);
                mma3p(acc[0][j], af[0], b0, b1);
                mma3p(acc[1][j], af[1], b0, b1);
            }
        }
        if (more) {
            __syncthreads();
#pragma unroll
            for (int u = 0; u < 4; u++) {
                st4(Asp, (ar + u * 32) * 36 + ac, pa[u]);
                st4(Bsp, br * 132 + bc + u * 32, pb[u]);
            }
            __syncthreads();
        }
    }

#pragma unroll
    for (int i = 0; i < 2; i++) {
        const int mA = m0 + wm * 32 + i * 16 + g;
#pragma unroll
        for (int half = 0; half < 2; half++) {
            const size_t m = mA + half * 8;
#pragma unroll
            for (int j = 0; j < 8; j++) {
                const int c = n0 + wn * 64 + j * 8 + tg * 2;
                float2 v = make_float2(acc[i][j][half * 2] + bias[c],
                                       acc[i][j][half * 2 + 1] + bias[c + 1]);
                *(float2*)&out[m * 768 + c] = v;
            }
        }
    }
}

// ---------------------------------------------------------------------------
extern "C" void kernel_launch(void* const* d_in, const int* in_sizes, int n_in,
                              void* d_out, int out_size) {
    const float* q     = (const float*)d_in[0];
    const float* k     = (const float*)d_in[1];
    const float* Wq    = (const float*)d_in[2];
    const float* Wkv   = (const float*)d_in[3];
    const float* Wproj = (const float*)d_in[4];
    const float* bproj = (const float*)d_in[5];
    float* out = (float*)d_out;

    const int smemG = (9216 + 8448) * 4;    // 70656 B
    const int smemA = 17664 * 4;            // 70656 B
    const int smemF = 12928 * 4;            // 51712 B
    cudaFuncSetAttribute(qkv_gemm, cudaFuncAttributeMaxDynamicSharedMemorySize, smemG);
    cudaFuncSetAttribute(proj_gemm, cudaFuncAttributeMaxDynamicSharedMemorySize, smemG);
    cudaFuncSetAttribute(attn_kernel, cudaFuncAttributeMaxDynamicSharedMemorySize, smemA);
    cudaFuncSetAttribute(fattn_kernel, cudaFuncAttributeMaxDynamicSharedMemorySize, smemF);

    qkv_gemm<<<dim3(18, 64), 256, smemG>>>(q, k, Wq, Wkv);
    fattn_kernel<<<96, 128, smemF>>>();
    attn_kernel<<<dim3(16, 96), 128, smemA>>>();
    proj_gemm<<<dim3(6, 64), 256, smemG>>>(Wproj, bproj, out);
}

// round 5
// speedup vs baseline: 1.4164x; 1.4164x over previous
#include <cuda_runtime.h>
#include <math.h>

#define NB 8
#define NSEQ 1024
#define NC 768
#define NH 12
#define NDH 64
#define SCALE 0.125f

// Scratch device globals
__device__ float g_qh[NB * NH * NSEQ * NDH];     // [B,H,N,64]
__device__ float g_kh[NB * NH * NSEQ * NDH];
__device__ float g_vh[NB * NH * NSEQ * NDH];
__device__ float g_fattn[NB * NH * NDH * NDH];   // [B,H,64,64]
__device__ float g_tmp[NB * NSEQ * NC];          // t + f, [B,N,C]

__device__ __forceinline__ unsigned f2tf(float x) {
    unsigned r;
    asm("cvt.rna.tf32.f32 %0, %1;" : "=r"(r) : "f"(x));
    return r;
}
__device__ __forceinline__ void split(float x, unsigned& hi, unsigned& lo) {
    unsigned h = f2tf(x);
    hi = h;
    lo = f2tf(x - __uint_as_float(h));
}
__device__ __forceinline__ void mma8(float d[4], const unsigned a[4],
                                     unsigned b0, unsigned b1) {
    asm volatile(
        "mma.sync.aligned.m16n8k8.row.col.f32.tf32.tf32.f32 "
        "{%0,%1,%2,%3}, {%4,%5,%6,%7}, {%8,%9}, {%0,%1,%2,%3};"
        : "+f"(d[0]), "+f"(d[1]), "+f"(d[2]), "+f"(d[3])
        : "r"(a[0]), "r"(a[1]), "r"(a[2]), "r"(a[3]), "r"(b0), "r"(b1));
}
__device__ __forceinline__ void mma3(float d[4],
                                     const unsigned ah[4], const unsigned al[4],
                                     unsigned bh0, unsigned bh1,
                                     unsigned bl0, unsigned bl1) {
    mma8(d, al, bh0, bh1);
    mma8(d, ah, bl0, bl1);
    mma8(d, ah, bh0, bh1);
}

// cp.async helpers
__device__ __forceinline__ unsigned smem_u32(const void* p) {
    return (unsigned)__cvta_generic_to_shared(p);
}
__device__ __forceinline__ void cpa16(unsigned dst, const void* src) {
    asm volatile("cp.async.ca.shared.global [%0], [%1], 16;" :: "r"(dst), "l"(src));
}
#define CP_COMMIT asm volatile("cp.async.commit_group;" ::: "memory")
#define CP_WAIT0  asm volatile("cp.async.wait_group 0;" ::: "memory")

// ---------------------------------------------------------------------------
// Kernel 1: fused QKV projection, 3xtf32, cp.async double-buffered tiles.
// dsm floats: A[2][128*36] at 0, B[2][32*136] at 9216. total 17920 f.
// ---------------------------------------------------------------------------
__global__ __launch_bounds__(256, 2) void qkv_gemm(const float* __restrict__ q,
                                                   const float* __restrict__ kx,
                                                   const float* __restrict__ Wq,
                                                   const float* __restrict__ Wkv) {
    extern __shared__ float dsm[];

    const int n0 = blockIdx.x * 128;
    const int m0 = blockIdx.y * 128;
    const bool isQ = (n0 < 768);
    const float* A = isQ ? q : kx;
    const float* Bm;
    int ldb, cb;
    if (isQ) { Bm = Wq;  ldb = 768;  cb = n0; }
    else     { Bm = Wkv; ldb = 1536; cb = n0 - 768; }

    const int t = threadIdx.x, lane = t & 31, w = t >> 5;
    const int g = lane >> 2, tg = lane & 3;
    const int wm = w & 3, wn = w >> 2;

    // staging indices
    const int aRow = t >> 1;               // 0..127  (2 float4 per row slice? no:)
    // A tile: 128x32 f32 = 1024 float4; thread does 4: idx = t + u*256
    // B tile: 32x128 f32 = 1024 float4
    auto stageA = [&](float* As, int k0) {
#pragma unroll
        for (int u = 0; u < 4; u++) {
            const int idx = t + u * 256;
            const int row = idx >> 3, colf = (idx & 7) * 4;
            cpa16(smem_u32(&As[row * 36 + colf]),
                  A + (size_t)(m0 + row) * 768 + k0 + colf);
        }
    };
    auto stageB = [&](float* Bs, int k0) {
#pragma unroll
        for (int u = 0; u < 4; u++) {
            const int idx = t + u * 256;
            const int row = idx >> 5, col = (idx & 31) * 4;
            cpa16(smem_u32(&Bs[row * 136 + col]),
                  Bm + (size_t)(k0 + row) * ldb + cb + col);
        }
    };

    float acc[2][8][4] = {};

    stageA(dsm, 0);
    stageB(dsm + 9216, 0);
    CP_COMMIT;
    CP_WAIT0;
    __syncthreads();

    for (int k0 = 0; k0 < 768; k0 += 32) {
        const int cur = (k0 >> 5) & 1;
        float* As = dsm + cur * 4608;
        float* Bs = dsm + 9216 + cur * 4352;
        const bool more = (k0 + 32 < 768);
        if (more) {
            stageA(dsm + (cur ^ 1) * 4608, k0 + 32);
            stageB(dsm + 9216 + (cur ^ 1) * 4352, k0 + 32);
            CP_COMMIT;
        }
#pragma unroll
        for (int kk = 0; kk < 4; kk++) {
            const int k = kk * 8;
            unsigned ah[2][4], al[2][4];
#pragma unroll
            for (int i = 0; i < 2; i++) {
                const int rb = wm * 32 + i * 16 + g;
                split(As[rb * 36 + k + tg],           ah[i][0], al[i][0]);
                split(As[(rb + 8) * 36 + k + tg],     ah[i][1], al[i][1]);
                split(As[rb * 36 + k + tg + 4],       ah[i][2], al[i][2]);
                split(As[(rb + 8) * 36 + k + tg + 4], ah[i][3], al[i][3]);
            }
#pragma unroll
            for (int j = 0; j < 8; j++) {
                const int c = wn * 64 + j * 8 + g;
                unsigned bh0, bl0, bh1, bl1;
                split(Bs[(k + tg) * 136 + c],     bh0, bl0);
                split(Bs[(k + tg + 4) * 136 + c], bh1, bl1);
                mma3(acc[0][j], ah[0], al[0], bh0, bh1, bl0, bl1);
                mma3(acc[1][j], ah[1], al[1], bh0, bh1, bl0, bl1);
            }
        }
        if (more) {
            CP_WAIT0;
            __syncthreads();
        }
    }

#pragma unroll
    for (int i = 0; i < 2; i++) {
        const int mA = m0 + wm * 32 + i * 16 + g;
#pragma unroll
        for (int half = 0; half < 2; half++) {
            const int m = mA + half * 8;
            const int bb = m >> 10, n = m & 1023;
#pragma unroll
            for (int j = 0; j < 8; j++) {
                const int cg = n0 + wn * 64 + j * 8 + tg * 2;
                float2 v = make_float2(acc[i][j][half * 2], acc[i][j][half * 2 + 1]);
                if (cg < 768) {
                    const int h = cg >> 6, d = cg & 63;
                    *(float2*)&g_qh[(((size_t)bb * NH + h) * NSEQ + n) * NDH + d] = v;
                } else {
                    const int cc = cg - 768;
                    const int c2 = (cc >= 768) ? cc - 768 : cc;
                    const int h = c2 >> 6, d = c2 & 63;
                    float* dst = (cc >= 768) ? g_vh : g_kh;
                    *(float2*)&dst[(((size_t)bb * NH + h) * NSEQ + n) * NDH + d] = v;
                }
            }
        }
    }
}

// ---------------------------------------------------------------------------
// Kernel 2: feature attention, 3xtf32 (static smem, small kernel).
// ---------------------------------------------------------------------------
__global__ __launch_bounds__(128) void fattn_kernel() {
    __shared__ float Qt[32 * 72];
    __shared__ float Kt[32 * 72];
    __shared__ float Ss[64 * 65];
    __shared__ float sinv[64];

    const int bh = blockIdx.x;
    const float* Q = g_qh + (size_t)bh * NSEQ * NDH;
    const float* K = g_kh + (size_t)bh * NSEQ * NDH;

    const int t = threadIdx.x, lane = t & 31, w = t >> 5;
    const int g = lane >> 2, tg = lane & 3;
    const int lr = t >> 4, lc = (t & 15) * 4;
    const int mb = w * 16 + g;

    float acc[8][4] = {};
    float4 pq[4], pk[4];

#pragma unroll
    for (int u = 0; u < 4; u++) {
        pq[u] = *(const float4*)(Q + (size_t)(lr + u * 8) * 64 + lc);
        pk[u] = *(const float4*)(K + (size_t)(lr + u * 8) * 64 + lc);
    }
#pragma unroll
    for (int u = 0; u < 4; u++) {
        *(float4*)&Qt[(lr + u * 8) * 72 + lc] = pq[u];
        *(float4*)&Kt[(lr + u * 8) * 72 + lc] = pk[u];
    }
    __syncthreads();

    for (int n0 = 32; n0 <= NSEQ; n0 += 32) {
        const bool more = (n0 < NSEQ);
        if (more) {
#pragma unroll
            for (int u = 0; u < 4; u++) {
                pq[u] = *(const float4*)(Q + (size_t)(n0 + lr + u * 8) * 64 + lc);
                pk[u] = *(const float4*)(K + (size_t)(n0 + lr + u * 8) * 64 + lc);
            }
        }
#pragma unroll
        for (int kk = 0; kk < 4; kk++) {
            const int k = kk * 8;
            unsigned ah[4], al[4];
            split(Qt[(k + tg) * 72 + mb],         ah[0], al[0]);
            split(Qt[(k + tg) * 72 + mb + 8],     ah[1], al[1]);
            split(Qt[(k + tg + 4) * 72 + mb],     ah[2], al[2]);
            split(Qt[(k + tg + 4) * 72 + mb + 8], ah[3], al[3]);
#pragma unroll
            for (int j = 0; j < 8; j++) {
                const int c = j * 8 + g;
                unsigned bh0, bl0, bh1, bl1;
                split(Kt[(k + tg) * 72 + c],     bh0, bl0);
                split(Kt[(k + tg + 4) * 72 + c], bh1, bl1);
                mma3(acc[j], ah, al, bh0, bh1, bl0, bl1);
            }
        }
        if (more) {
            __syncthreads();
#pragma unroll
            for (int u = 0; u < 4; u++) {
                *(float4*)&Qt[(lr + u * 8) * 72 + lc] = pq[u];
                *(float4*)&Kt[(lr + u * 8) * 72 + lc] = pk[u];
            }
            __syncthreads();
        }
    }

#pragma unroll
    for (int j = 0; j < 8; j++) {
        const int r0 = w * 16 + g, c = j * 8 + tg * 2;
        Ss[r0 * 65 + c]           = acc[j][0] * SCALE;
        Ss[r0 * 65 + c + 1]       = acc[j][1] * SCALE;
        Ss[(r0 + 8) * 65 + c]     = acc[j][2] * SCALE;
        Ss[(r0 + 8) * 65 + c + 1] = acc[j][3] * SCALE;
    }
    __syncthreads();
    if (t < 64) {
        float mx = -INFINITY;
        for (int e = 0; e < 64; e++) mx = fmaxf(mx, Ss[t * 65 + e]);
        float s = 0.f;
        for (int e = 0; e < 64; e++) {
            float v = __expf(Ss[t * 65 + e] - mx);
            Ss[t * 65 + e] = v;
            s += v;
        }
        sinv[t] = 1.0f / s;
    }
    __syncthreads();
    float* outp = g_fattn + (size_t)bh * 4096;
    for (int idx = t; idx < 4096; idx += 128) {
        const int r = idx >> 6;
        outp[idx] = Ss[r * 65 + (idx & 63)] * sinv[r];
    }
}

// ---------------------------------------------------------------------------
// Kernel 3: flash attention + feature apply, 3xtf32, cp.async double-buffered K/V.
// dsm floats: Qs 64*68 at 0 (4352; later Fa)
//             Ks[2] 32*68 at 4352 (+b*2176; later Vq spans 4352..8704)
//             Vs[2] 32*72 at 8704 (+b*2304)
//             Ps 4w*16*36 at 13312.  total 15616 f.
// ---------------------------------------------------------------------------
__global__ __launch_bounds__(128) void attn_kernel() {
    extern __shared__ float dsm[];
    float* Qs = dsm;

    const int bh = blockIdx.y;
    const int n0q = blockIdx.x * 64;
    const float* Qg = g_qh + (size_t)bh * NSEQ * NDH;
    const float* Kg = g_kh + (size_t)bh * NSEQ * NDH;
    const float* Vg = g_vh + (size_t)bh * NSEQ * NDH;

    const int t = threadIdx.x, lane = t & 31, w = t >> 5;
    const int g = lane >> 2, tg = lane & 3;

    auto stageKV = [&](int buf, int c0) {
        float* Ks = dsm + 4352 + buf * 2176;
        float* Vs = dsm + 8704 + buf * 2304;
#pragma unroll
        for (int u = 0; u < 4; u++) {
            const int idx = t + u * 128;
            const int row = idx >> 4, colf = (idx & 15) * 4;
            cpa16(smem_u32(&Ks[row * 68 + colf]),
                  Kg + (size_t)(c0 + row) * 64 + colf);
            cpa16(smem_u32(&Vs[row * 72 + colf]),
                  Vg + (size_t)(c0 + row) * 64 + colf);
        }
    };

    // stage Q via cp.async
#pragma unroll
    for (int u = 0; u < 8; u++) {
        const int idx = t + u * 128;
        const int row = idx >> 4, colf = (idx & 15) * 4;
        cpa16(smem_u32(&Qs[row * 68 + colf]),
              Qg + (size_t)(n0q + row) * 64 + colf);
    }
    stageKV(0, 0);
    CP_COMMIT;
    CP_WAIT0;
    __syncthreads();

    // Q fragments (pre-split) to registers
    unsigned qfh[8][4], qfl[8][4];
    {
        const int rb = w * 16 + g;
#pragma unroll
        for (int kk = 0; kk < 8; kk++) {
            const int k = kk * 8;
            split(Qs[rb * 68 + k + tg],           qfh[kk][0], qfl[kk][0]);
            split(Qs[(rb + 8) * 68 + k + tg],     qfh[kk][1], qfl[kk][1]);
            split(Qs[rb * 68 + k + tg + 4],       qfh[kk][2], qfl[kk][2]);
            split(Qs[(rb + 8) * 68 + k + tg + 4], qfh[kk][3], qfl[kk][3]);
        }
    }

    float O[8][4] = {};
    float mr0 = -INFINITY, mr1 = -INFINITY, l0 = 0.f, l1 = 0.f;
    float* Pw = dsm + 13312 + w * 576;

    for (int c0 = 0; c0 < NSEQ; c0 += 32) {
        const int cur = (c0 >> 5) & 1;
        float* Ks = dsm + 4352 + cur * 2176;
        float* Vs = dsm + 8704 + cur * 2304;
        const bool more = (c0 + 32 < NSEQ);
        if (more) {
            stageKV(cur ^ 1, c0 + 32);
            CP_COMMIT;
        }

        // S = Q K^T
        float sacc[4][4] = {};
#pragma unroll
        for (int kk = 0; kk < 8; kk++) {
            const int k = kk * 8;
#pragma unroll
            for (int j = 0; j < 4; j++) {
                const int c = j * 8 + g;
                unsigned bh0, bl0, bh1, bl1;
                split(Ks[c * 68 + k + tg],     bh0, bl0);
                split(Ks[c * 68 + k + tg + 4], bh1, bl1);
                mma3(sacc[j], qfh[kk], qfl[kk], bh0, bh1, bl0, bl1);
            }
        }

        // online softmax (rows g and g+8)
        float mx0 = -INFINITY, mx1 = -INFINITY;
#pragma unroll
        for (int j = 0; j < 4; j++) {
#pragma unroll
            for (int u = 0; u < 4; u++) sacc[j][u] *= SCALE;
            mx0 = fmaxf(mx0, fmaxf(sacc[j][0], sacc[j][1]));
            mx1 = fmaxf(mx1, fmaxf(sacc[j][2], sacc[j][3]));
        }
        mx0 = fmaxf(mx0, __shfl_xor_sync(0xffffffffu, mx0, 1));
        mx0 = fmaxf(mx0, __shfl_xor_sync(0xffffffffu, mx0, 2));
        mx1 = fmaxf(mx1, __shfl_xor_sync(0xffffffffu, mx1, 1));
        mx1 = fmaxf(mx1, __shfl_xor_sync(0xffffffffu, mx1, 2));
        const float mn0 = fmaxf(mr0, mx0), mn1 = fmaxf(mr1, mx1);
        const float co0 = __expf(mr0 - mn0), co1 = __expf(mr1 - mn1);
        float rs0 = 0.f, rs1 = 0.f;
#pragma unroll
        for (int j = 0; j < 4; j++) {
            const float p00 = __expf(sacc[j][0] - mn0);
            const float p01 = __expf(sacc[j][1] - mn0);
            const float p10 = __expf(sacc[j][2] - mn1);
            const float p11 = __expf(sacc[j][3] - mn1);
            rs0 += p00 + p01;
            rs1 += p10 + p11;
            const int c = j * 8 + tg * 2;
            Pw[g * 36 + c]           = p00;
            Pw[g * 36 + c + 1]       = p01;
            Pw[(g + 8) * 36 + c]     = p10;
            Pw[(g + 8) * 36 + c + 1] = p11;
        }
        rs0 += __shfl_xor_sync(0xffffffffu, rs0, 1);
        rs0 += __shfl_xor_sync(0xffffffffu, rs0, 2);
        rs1 += __shfl_xor_sync(0xffffffffu, rs1, 1);
        rs1 += __shfl_xor_sync(0xffffffffu, rs1, 2);
        l0 = l0 * co0 + rs0;
        l1 = l1 * co1 + rs1;
        mr0 = mn0;
        mr1 = mn1;
#pragma unroll
        for (int nt = 0; nt < 8; nt++) {
            O[nt][0] *= co0; O[nt][1] *= co0;
            O[nt][2] *= co1; O[nt][3] *= co1;
        }
        __syncwarp();

        // O += P @ V
#pragma unroll
        for (int kk = 0; kk < 4; kk++) {
            const int k = kk * 8;
            unsigned ah[4], al[4];
            split(Pw[g * 36 + k + tg],           ah[0], al[0]);
            split(Pw[(g + 8) * 36 + k + tg],     ah[1], al[1]);
            split(Pw[g * 36 + k + tg + 4],       ah[2], al[2]);
            split(Pw[(g + 8) * 36 + k + tg + 4], ah[3], al[3]);
#pragma unroll
            for (int nt = 0; nt < 8; nt++) {
                unsigned bh0, bl0, bh1, bl1;
                split(Vs[(k + tg) * 72 + nt * 8 + g],     bh0, bl0);
                split(Vs[(k + tg + 4) * 72 + nt * 8 + g], bh1, bl1);
                mma3(O[nt], ah, al, bh0, bh1, bl0, bl1);
            }
        }

        if (more) {
            CP_WAIT0;
        }
        __syncthreads();
    }

    // normalize token attention
    const float i0 = 1.0f / l0, i1 = 1.0f / l1;
#pragma unroll
    for (int nt = 0; nt < 8; nt++) {
        O[nt][0] *= i0; O[nt][1] *= i0;
        O[nt][2] *= i1; O[nt][3] *= i1;
    }

    // feature path: O[n,d] += sum_e V[n,e] * f_attn[d,e]
    float* Fa = dsm;            // [d][e] stride 68
    float* Vq = dsm + 4352;     // [r][e] stride 68
    const float* Fg = g_fattn + (size_t)bh * 4096;
    {
        const int lr = t >> 4, lc = (t & 15) * 4;
#pragma unroll
        for (int u = 0; u < 8; u++) {
            const int row = lr + u * 8;
            *(float4*)&Fa[row * 68 + lc] = *(const float4*)(Fg + (size_t)row * 64 + lc);
            *(float4*)&Vq[row * 68 + lc] =
                *(const float4*)(Vg + (size_t)(n0q + row) * 64 + lc);
        }
    }
    __syncthreads();
    {
        const int rb = w * 16 + g;
#pragma unroll
        for (int kk = 0; kk < 8; kk++) {
            const int k = kk * 8;
            unsigned ah[4], al[4];
            split(Vq[rb * 68 + k + tg],           ah[0], al[0]);
            split(Vq[(rb + 8) * 68 + k + tg],     ah[1], al[1]);
            split(Vq[rb * 68 + k + tg + 4],       ah[2], al[2]);
            split(Vq[(rb + 8) * 68 + k + tg + 4], ah[3], al[3]);
#pragma unroll
            for (int nt = 0; nt < 8; nt++) {
                unsigned bh0, bl0, bh1, bl1;
                split(Fa[(nt * 8 + g) * 68 + k + tg],     bh0, bl0);
                split(Fa[(nt * 8 + g) * 68 + k + tg + 4], bh1, bl1);
                mma3(O[nt], ah, al, bh0, bh1, bl0, bl1);
            }
        }
    }

    // store t+f into [B,N,C]
    const int bb = bh / NH, h = bh - bb * NH;
    const int r0 = n0q + w * 16 + g;
#pragma unroll
    for (int nt = 0; nt < 8; nt++) {
        const int col = h * 64 + nt * 8 + tg * 2;
        *(float2*)&g_tmp[((size_t)bb * NSEQ + r0) * NC + col] =
            make_float2(O[nt][0], O[nt][1]);
        *(float2*)&g_tmp[((size_t)bb * NSEQ + r0 + 8) * NC + col] =
            make_float2(O[nt][2], O[nt][3]);
    }
}

// ---------------------------------------------------------------------------
// Kernel 4: output projection, 3xtf32, cp.async double-buffered tiles.
// ---------------------------------------------------------------------------
__global__ __launch_bounds__(256, 2) void proj_gemm(const float* __restrict__ W,
                                                    const float* __restrict__ bias,
                                                    float* __restrict__ out) {
    extern __shared__ float dsm[];

    const int n0 = blockIdx.x * 128;
    const int m0 = blockIdx.y * 128;
    const int t = threadIdx.x, lane = t & 31, w = t >> 5;
    const int g = lane >> 2, tg = lane & 3;
    const int wm = w & 3, wn = w >> 2;

    auto stageA = [&](float* As, int k0) {
#pragma unroll
        for (int u = 0; u < 4; u++) {
            const int idx = t + u * 256;
            const int row = idx >> 3, colf = (idx & 7) * 4;
            cpa16(smem_u32(&As[row * 36 + colf]),
                  g_tmp + (size_t)(m0 + row) * 768 + k0 + colf);
        }
    };
    auto stageB = [&](float* Bs, int k0) {
#pragma unroll
        for (int u = 0; u < 4; u++) {
            const int idx = t + u * 256;
            const int row = idx >> 5, col = (idx & 31) * 4;
            cpa16(smem_u32(&Bs[row * 136 + col]),
                  W + (size_t)(k0 + row) * 768 + n0 + col);
        }
    };

    float acc[2][8][4] = {};

    stageA(dsm, 0);
    stageB(dsm + 9216, 0);
    CP_COMMIT;
    CP_WAIT0;
    __syncthreads();

    for (int k0 = 0; k0 < 768; k0 += 32) {
        const int cur = (k0 >> 5) & 1;
        float* As = dsm + cur * 4608;
        float* Bs = dsm + 9216 + cur * 4352;
        const bool more = (k0 + 32 < 768);
        if (more) {
            stageA(dsm + (cur ^ 1) * 4608, k0 + 32);
            stageB(dsm + 9216 + (cur ^ 1) * 4352, k0 + 32);
            CP_COMMIT;
        }
#pragma unroll
        for (int kk = 0; kk < 4; kk++) {
            const int k = kk * 8;
            unsigned ah[2][4], al[2][4];
#pragma unroll
            for (int i = 0; i < 2; i++) {
                const int rb = wm * 32 + i * 16 + g;
                split(As[rb * 36 + k + tg],           ah[i][0], al[i][0]);
                split(As[(rb + 8) * 36 + k + tg],     ah[i][1], al[i][1]);
                split(As[rb * 36 + k + tg + 4],       ah[i][2], al[i][2]);
                split(As[(rb + 8) * 36 + k + tg + 4], ah[i][3], al[i][3]);
            }
#pragma unroll
            for (int j = 0; j < 8; j++) {
                const int c = wn * 64 + j * 8 + g;
                unsigned bh0, bl0, bh1, bl1;
                split(Bs[(k + tg) * 136 + c],     bh0, bl0);
                split(Bs[(k + tg + 4) * 136 + c], bh1, bl1);
                mma3(acc[0][j], ah[0], al[0], bh0, bh1, bl0, bl1);
                mma3(acc[1][j], ah[1], al[1], bh0, bh1, bl0, bl1);
            }
        }
        if (more) {
            CP_WAIT0;
            __syncthreads();
        }
    }

#pragma unroll
    for (int i = 0; i < 2; i++) {
        const int mA = m0 + wm * 32 + i * 16 + g;
#pragma unroll
        for (int half = 0; half < 2; half++) {
            const size_t m = mA + half * 8;
#pragma unroll
            for (int j = 0; j < 8; j++) {
                const int c = n0 + wn * 64 + j * 8 + tg * 2;
                float2 v = make_float2(acc[i][j][half * 2] + bias[c],
                                       acc[i][j][half * 2 + 1] + bias[c + 1]);
                *(float2*)&out[m * 768 + c] = v;
            }
        }
    }
}

// ---------------------------------------------------------------------------
extern "C" void kernel_launch(void* const* d_in, const int* in_sizes, int n_in,
                              void* d_out, int out_size) {
    const float* q     = (const float*)d_in[0];
    const float* k     = (const float*)d_in[1];
    const float* Wq    = (const float*)d_in[2];
    const float* Wkv   = (const float*)d_in[3];
    const float* Wproj = (const float*)d_in[4];
    const float* bproj = (const float*)d_in[5];
    float* out = (float*)d_out;

    const int smemG = 17920 * 4;   // 71680 B
    const int smemA = 15616 * 4;   // 62464 B
    cudaFuncSetAttribute(qkv_gemm, cudaFuncAttributeMaxDynamicSharedMemorySize, smemG);
    cudaFuncSetAttribute(proj_gemm, cudaFuncAttributeMaxDynamicSharedMemorySize, smemG);
    cudaFuncSetAttribute(attn_kernel, cudaFuncAttributeMaxDynamicSharedMemorySize, smemA);

    qkv_gemm<<<dim3(18, 64), 256, smemG>>>(q, k, Wq, Wkv);
    fattn_kernel<<<96, 128>>>();
    attn_kernel<<<dim3(16, 96), 128, smemA>>>();
    proj_gemm<<<dim3(6, 64), 256, smemG>>>(Wproj, bproj, out);
}